// round 4
// baseline (speedup 1.0000x reference)
#include <cuda_runtime.h>

#define NODES_MAX 50000
#define EDGES_MAX 800000
#define D 128

typedef unsigned long long ull;

// Scratch (allocation-free rule: __device__ globals)
__device__ float g_A[(size_t)NODES_MAX * D];    // aggregated raw features, 25.6 MB
__device__ int   g_deg[NODES_MAX];
__device__ int   g_rowptr[NODES_MAX + 1];
__device__ int   g_cursor[NODES_MAX];
__device__ int   g_esrc[EDGES_MAX];             // src ids, sorted by dst

#define FMA2(d, a, b) \
    asm("fma.rn.f32x2 %0, %1, %2, %0;" : "+l"(d) : "l"(a), "l"(b))

__device__ __forceinline__ ull pack2(float x, float y) {
    ull r; asm("mov.b64 %0, {%1, %2};" : "=l"(r) : "f"(x), "f"(y)); return r;
}
__device__ __forceinline__ float2 unpack2(ull v) {
    float2 r; asm("mov.b64 {%0, %1}, %2;" : "=f"(r.x), "=f"(r.y) : "l"(v)); return r;
}

// ---------------------------------------------------------------- CSR build
__global__ void zero_deg(int N) {
    int i = blockIdx.x * blockDim.x + threadIdx.x;
    if (i < N) g_deg[i] = 0;
}

__global__ void hist_dst(const int* __restrict__ dst, int E) {
    int i = blockIdx.x * blockDim.x + threadIdx.x;
    int stride = gridDim.x * blockDim.x;
    for (; i < E; i += stride) atomicAdd(&g_deg[dst[i]], 1);
}

// Single-block exclusive scan of g_deg -> g_rowptr / g_cursor
__global__ void scan_deg(int N) {
    __shared__ int part[1024];
    const int t = threadIdx.x;
    const int C = (N + 1023) / 1024;
    int beg = t * C;
    int end = min(beg + C, N);
    int s = 0;
    for (int j = beg; j < end; j++) s += g_deg[j];
    part[t] = s;
    __syncthreads();
    // Hillis-Steele inclusive scan over 1024 partials
    for (int off = 1; off < 1024; off <<= 1) {
        int v = part[t];
        int add = (t >= off) ? part[t - off] : 0;
        __syncthreads();
        part[t] = v + add;
        __syncthreads();
    }
    int run = (t > 0) ? part[t - 1] : 0;  // exclusive prefix of this chunk
    for (int j = beg; j < end; j++) {
        int d = g_deg[j];
        g_rowptr[j] = run;
        g_cursor[j] = run;
        run += d;
    }
    if (t == 1023) g_rowptr[N] = part[1023];
}

__global__ void reorder_edges(const int* __restrict__ src,
                              const int* __restrict__ dst, int E) {
    int i = blockIdx.x * blockDim.x + threadIdx.x;
    int stride = gridDim.x * blockDim.x;
    for (; i < E; i += stride) {
        int d = dst[i];
        int pos = atomicAdd(&g_cursor[d], 1);
        g_esrc[pos] = src[i];
    }
}

// ------------------------------------------------- gather-reduce (warp/node)
// A[v] = sum over in-edges of feat[src]. Lane owns one float4 of the 512B row.
__global__ void aggregate(const float* __restrict__ feat, int N) {
    const int gw = (int)((blockIdx.x * blockDim.x + threadIdx.x) >> 5);
    const int lane = threadIdx.x & 31;
    if (gw >= N) return;
    const float4* f4 = (const float4*)feat;

    int beg = g_rowptr[gw];
    int end = g_rowptr[gw + 1];
    float4 acc = make_float4(0.f, 0.f, 0.f, 0.f);

    int j = beg;
    for (; j + 4 <= end; j += 4) {
        int s0 = __ldg(g_esrc + j);
        int s1 = __ldg(g_esrc + j + 1);
        int s2 = __ldg(g_esrc + j + 2);
        int s3 = __ldg(g_esrc + j + 3);
        float4 v0 = f4[(size_t)s0 * 32 + lane];
        float4 v1 = f4[(size_t)s1 * 32 + lane];
        float4 v2 = f4[(size_t)s2 * 32 + lane];
        float4 v3 = f4[(size_t)s3 * 32 + lane];
        acc.x += v0.x + v1.x + v2.x + v3.x;
        acc.y += v0.y + v1.y + v2.y + v3.y;
        acc.z += v0.z + v1.z + v2.z + v3.z;
        acc.w += v0.w + v1.w + v2.w + v3.w;
    }
    for (; j < end; j++) {
        int s = __ldg(g_esrc + j);
        float4 v = f4[(size_t)s * 32 + lane];
        acc.x += v.x; acc.y += v.y; acc.z += v.z; acc.w += v.w;
    }
    ((float4*)g_A)[(size_t)gw * 32 + lane] = acc;
}

// ------------------------------------------------------------- fused GEMM
// out[N,128] = A @ W + feat @ LW + bias   (K = 256, two 128-phases)
// Block: 64 rows x 128 cols, 256 threads. Thread: 8 rows x 2 col-pairs.
// cg = t&31 -> pairs {cg, cg+32} -> cols {2cg,2cg+1, 2cg+64,2cg+65}
// rg = t>>5 -> rows rg + r*8, r=0..7
__global__ void gemm_fused(const float* __restrict__ feat,
                           const float* __restrict__ W,
                           const float* __restrict__ LW,
                           const float* __restrict__ bias,
                           float* __restrict__ out, int N) {
    const int KC = 16;
    __shared__ ull ws2[KC][64];   // weight col-pairs, 8 KB
    __shared__ ull fs2[64][KC];   // duplicated input values (v,v), 8 KB
    const int t = threadIdx.x;
    const int row0 = blockIdx.x * 64;
    const int cg = t & 31;
    const int rg = t >> 5;

    ull acc[8][2];
#pragma unroll
    for (int r = 0; r < 8; r++) { acc[r][0] = 0ull; acc[r][1] = 0ull; }

    for (int kc = 0; kc < 256; kc += KC) {
        const bool ph0 = (kc < 128);
        const float* in0 = ph0 ? g_A : feat;
        const float* Wsel = ph0 ? W : LW;
        const int kl = kc & 127;

        // weight chunk: 16 k-rows x 64 col-pairs
        for (int i = t; i < KC * 64; i += 256) {
            int k = i >> 6, p = i & 63;
            float2 w = *(const float2*)&Wsel[(size_t)(kl + k) * D + 2 * p];
            ws2[k][p] = pack2(w.x, w.y);
        }
        // input chunk: 64 rows x 16 k, duplicated into both packed lanes
        for (int i = t; i < 64 * KC; i += 256) {
            int r = i >> 4, k = i & 15;
            int grow = row0 + r;
            float f = (grow < N) ? in0[(size_t)grow * D + kl + k] : 0.0f;
            fs2[r][k] = pack2(f, f);
        }
        __syncthreads();

#pragma unroll
        for (int k = 0; k < KC; k++) {
            ull w0 = ws2[k][cg];
            ull w1 = ws2[k][cg + 32];
#pragma unroll
            for (int r = 0; r < 8; r++) {
                ull f = fs2[rg + r * 8][k];
                FMA2(acc[r][0], f, w0);
                FMA2(acc[r][1], f, w1);
            }
        }
        __syncthreads();
    }

    float2 b0 = *(const float2*)&bias[2 * cg];
    float2 b1 = *(const float2*)&bias[2 * cg + 64];
#pragma unroll
    for (int r = 0; r < 8; r++) {
        int grow = row0 + rg + r * 8;
        if (grow >= N) continue;
        float2 o0 = unpack2(acc[r][0]);
        float2 o1 = unpack2(acc[r][1]);
        o0.x += b0.x; o0.y += b0.y;
        o1.x += b1.x; o1.y += b1.y;
        *(float2*)&out[(size_t)grow * D + 2 * cg]      = o0;
        *(float2*)&out[(size_t)grow * D + 2 * cg + 64] = o1;
    }
}

extern "C" void kernel_launch(void* const* d_in, const int* in_sizes, int n_in,
                              void* d_out, int out_size) {
    const float* feat = (const float*)d_in[0];   // [N, 128]
    const float* W    = (const float*)d_in[1];   // [128, 128]
    const float* bias = (const float*)d_in[2];   // [128]
    const float* LW   = (const float*)d_in[3];   // [128, 128]
    const int*   src  = (const int*)d_in[4];     // [E]
    const int*   dst  = (const int*)d_in[5];     // [E]
    float* out = (float*)d_out;                  // [N, 128]

    const int N = in_sizes[0] / D;
    const int E = in_sizes[4];

    // CSR build (dst-sorted edge list)
    zero_deg<<<(N + 255) / 256, 256>>>(N);
    hist_dst<<<512, 256>>>(dst, E);
    scan_deg<<<1, 1024>>>(N);
    reorder_edges<<<512, 256>>>(src, dst, E);

    // A[v] = sum_{e: dst=v} feat[src_e]
    aggregate<<<(N + 7) / 8, 256>>>(feat, N);

    // out = A @ W + feat @ LW + bias
    gemm_fused<<<(N + 63) / 64, 256>>>(feat, W, LW, bias, out, N);
}

// round 6
// speedup vs baseline: 1.4936x; 1.4936x over previous
#include <cuda_runtime.h>

#define NODES_MAX 50000
#define D 128

typedef unsigned long long ull;

// 25.6 MB scratch for feat @ W (allocation-free rule: __device__ global)
__device__ float g_transformed[(size_t)NODES_MAX * D];

#define FMA2(d, a, b) \
    asm("fma.rn.f32x2 %0, %1, %2, %0;" : "+l"(d) : "l"(a), "l"(b))

__device__ __forceinline__ ull pack2(float x, float y) {
    ull r; asm("mov.b64 %0, {%1, %2};" : "=l"(r) : "f"(x), "f"(y)); return r;
}
__device__ __forceinline__ float2 unpack2(ull v) {
    float2 r; asm("mov.b64 {%0, %1}, %2;" : "=f"(r.x), "=f"(r.y) : "l"(v)); return r;
}

// ------------------------------------------------------------- fused GEMM
// One pass over feat produces 256 output columns:
//   cols   0..127 -> T  = feat @ W        (scratch for the edge scatter)
//   cols 128..255 -> out = feat @ LW + bias
// Block: 64 rows x 256 cols, 256 threads.
// Thread t: cg = t&31 owns col-pairs {cg, cg+32, cg+64, cg+96} (8 columns),
//           rg = t>>5 owns rows rg + 8r, r = 0..7.
// Core uses packed fma.rn.f32x2 (FFMA2): 2 fp32 FMAs per instruction,
// halving the FMA-issue floor vs scalar FFMA.
__global__ __launch_bounds__(256, 2)
void gemm_fused(const float* __restrict__ feat,
                const float* __restrict__ W,
                const float* __restrict__ LW,
                const float* __restrict__ bias,
                float* __restrict__ out, int N) {
    const int KC = 16;
    __shared__ ull ws2[KC][128];  // 128 col-pairs of [W | LW], 16 KB
    __shared__ ull fs2[64][KC];   // feat values duplicated (v,v), 8 KB
    const int t = threadIdx.x;
    const int row0 = blockIdx.x * 64;
    const int cg = t & 31;
    const int rg = t >> 5;

    ull acc[8][4];
#pragma unroll
    for (int r = 0; r < 8; r++)
#pragma unroll
        for (int c = 0; c < 4; c++) acc[r][c] = 0ull;

    for (int kc = 0; kc < D; kc += KC) {
        // Weight chunk: 16 k-rows x 128 col-pairs ([W | LW] side by side)
#pragma unroll
        for (int i = 0; i < 8; i++) {
            int idx = t + i * 256;        // 0 .. 2047
            int k = idx >> 7, p = idx & 127;
            float2 w = (p < 64)
                ? *(const float2*)&W[(size_t)(kc + k) * D + 2 * p]
                : *(const float2*)&LW[(size_t)(kc + k) * D + 2 * (p - 64)];
            ws2[k][p] = pack2(w.x, w.y);
        }
        // Feat chunk: 64 rows x 16 k, duplicated into both packed lanes
#pragma unroll
        for (int i = 0; i < 4; i++) {
            int idx = t + i * 256;        // 0 .. 1023
            int r = idx >> 4, k = idx & 15;
            int grow = row0 + r;
            float f = (grow < N) ? feat[(size_t)grow * D + kc + k] : 0.0f;
            fs2[r][k] = pack2(f, f);
        }
        __syncthreads();

#pragma unroll
        for (int k = 0; k < KC; k++) {
            ull w0 = ws2[k][cg];
            ull w1 = ws2[k][cg + 32];
            ull w2 = ws2[k][cg + 64];
            ull w3 = ws2[k][cg + 96];
#pragma unroll
            for (int r = 0; r < 8; r++) {
                ull f = fs2[rg + r * 8][k];   // warp-wide broadcast
                FMA2(acc[r][0], f, w0);
                FMA2(acc[r][1], f, w1);
                FMA2(acc[r][2], f, w2);
                FMA2(acc[r][3], f, w3);
            }
        }
        __syncthreads();
    }

    float2 b0 = *(const float2*)&bias[2 * cg];
    float2 b1 = *(const float2*)&bias[2 * cg + 64];
#pragma unroll
    for (int r = 0; r < 8; r++) {
        int grow = row0 + rg + r * 8;
        if (grow >= N) continue;
        // pairs 0..63  -> T (cols 0..127)
        float2 t0 = unpack2(acc[r][0]);
        float2 t1 = unpack2(acc[r][1]);
        *(float2*)&g_transformed[(size_t)grow * D + 2 * cg]      = t0;
        *(float2*)&g_transformed[(size_t)grow * D + 2 * cg + 64] = t1;
        // pairs 64..127 -> out (cols 0..127 of output) + bias
        float2 o0 = unpack2(acc[r][2]);
        float2 o1 = unpack2(acc[r][3]);
        o0.x += b0.x; o0.y += b0.y;
        o1.x += b1.x; o1.y += b1.y;
        *(float2*)&out[(size_t)grow * D + 2 * cg]      = o0;
        *(float2*)&out[(size_t)grow * D + 2 * cg + 64] = o1;
    }
}

// Edge scatter: one warp per edge-quad. Each lane owns a float4 (16 B) of the
// 512 B row. All 4 gather loads issued before any reduction (MLP=4), then
// 4 vectorized L2 reductions (red.global.add.v4.f32, no return trip).
// L2-resident (T + out = 51 MB < 126 MB L2); measured at the LTS cap.
__global__ void scatter_edges(const int* __restrict__ src,
                              const int* __restrict__ dst,
                              float* __restrict__ out, int E) {
    const int EPW = 4;
    const int gw = (int)((blockIdx.x * blockDim.x + threadIdx.x) >> 5);
    const int lane = threadIdx.x & 31;
    const int e0 = gw * EPW;
    if (e0 >= E) return;
    const int cnt = (E - e0 < EPW) ? (E - e0) : EPW;

    float4 v[EPW];
    float* p[EPW];
#pragma unroll
    for (int i = 0; i < EPW; i++) {
        if (i < cnt) {
            int s = __ldg(src + e0 + i);
            int d = __ldg(dst + e0 + i);
            v[i] = *reinterpret_cast<const float4*>(
                g_transformed + (size_t)s * D + lane * 4);
            p[i] = out + (size_t)d * D + lane * 4;
        }
    }
#pragma unroll
    for (int i = 0; i < EPW; i++) {
        if (i < cnt) {
            asm volatile(
                "red.global.add.v4.f32 [%0], {%1, %2, %3, %4};"
                :: "l"(p[i]), "f"(v[i].x), "f"(v[i].y), "f"(v[i].z), "f"(v[i].w)
                : "memory");
        }
    }
}

extern "C" void kernel_launch(void* const* d_in, const int* in_sizes, int n_in,
                              void* d_out, int out_size) {
    const float* feat = (const float*)d_in[0];   // [N, 128]
    const float* W    = (const float*)d_in[1];   // [128, 128]
    const float* bias = (const float*)d_in[2];   // [128]
    const float* LW   = (const float*)d_in[3];   // [128, 128]
    const int*   src  = (const int*)d_in[4];     // [E]
    const int*   dst  = (const int*)d_in[5];     // [E]
    float* out = (float*)d_out;                  // [N, 128]

    const int N = in_sizes[0] / D;
    const int E = in_sizes[4];

    // 1) T = feat@W (scratch) ; out = feat@LW + bias
    gemm_fused<<<(N + 63) / 64, 256>>>(feat, W, LW, bias, out, N);

    // 2) out[dst] += T[src]
    const int warps = (E + 3) / 4;
    const int blocks = (warps * 32 + 255) / 256;
    scatter_edges<<<blocks, 256>>>(src, dst, out, E);
}

// round 10
// speedup vs baseline: 2.2973x; 1.5381x over previous
#include <cuda_runtime.h>
#include <cuda_bf16.h>
#include <cstdint>

#define NODES_MAX 50000
#define D 128

typedef unsigned long long ull;

// ---------------- scratch (__device__ globals: allocation-free rule) --------
__device__ float g_transformed[(size_t)NODES_MAX * D];   // T = feat @ W
// Pre-split weights, transposed to [n][k] (B^T layout), bf16 hi/lo
__device__ __nv_bfloat16 g_BhW[128 * 128];
__device__ __nv_bfloat16 g_BlW[128 * 128];
__device__ __nv_bfloat16 g_BhL[128 * 128];
__device__ __nv_bfloat16 g_BlL[128 * 128];

// ---------------- prep: [W|LW]^T -> bf16 hi/lo ------------------------------
__global__ void prep_B(const float* __restrict__ W, const float* __restrict__ LW) {
    int i = blockIdx.x * blockDim.x + threadIdx.x;
    if (i >= 32768) return;
    const float* M = (i < 16384) ? W : LW;
    __nv_bfloat16* Bh = (i < 16384) ? g_BhW : g_BhL;
    __nv_bfloat16* Bl = (i < 16384) ? g_BlW : g_BlL;
    int j = i & 16383;
    int n = j >> 7, k = j & 127;
    float w = M[k * 128 + n];                 // transpose: B^T[n][k] = W[k][n]
    __nv_bfloat16 hi = __float2bfloat16(w);
    __nv_bfloat16 lo = __float2bfloat16(w - __bfloat162float(hi));
    Bh[n * 128 + k] = hi;
    Bl[n * 128 + k] = lo;
}

// ---------------- helpers ---------------------------------------------------
__device__ __forceinline__ uint32_t smem_u32(const void* p) {
    uint32_t a;
    asm("{ .reg .u64 t; cvta.to.shared.u64 t, %1; cvt.u32.u64 %0, t; }"
        : "=r"(a) : "l"(p));
    return a;
}

#define LDSM_X4(r0, r1, r2, r3, a) \
    asm volatile("ldmatrix.sync.aligned.m8n8.x4.shared.b16 {%0,%1,%2,%3}, [%4];" \
        : "=r"(r0), "=r"(r1), "=r"(r2), "=r"(r3) : "r"(a))

#define MMA16816(d, a, b0, b1) \
    asm volatile("mma.sync.aligned.m16n8k16.row.col.f32.bf16.bf16.f32 " \
        "{%0,%1,%2,%3}, {%4,%5,%6,%7}, {%8,%9}, {%0,%1,%2,%3};" \
        : "+f"((d)[0]), "+f"((d)[1]), "+f"((d)[2]), "+f"((d)[3]) \
        : "r"((a)[0]), "r"((a)[1]), "r"((a)[2]), "r"((a)[3]), \
          "r"(b0), "r"(b1))

// ---------------- tensor-core (mma.sync) fused GEMM -------------------------
// Grid (782, 2). blockIdx.y = 0: cols = W -> g_transformed
//                blockIdx.y = 1: cols = LW -> out (+bias)
// CTA: 256 threads, 64 rows x 128 cols. Warp (w = wm*4 + wn): 32x32 tile.
// Precision: A,B split to bf16 hi/lo; D = AhBh + AlBh + AhBl, fp32 accum.
// SMEM rows padded to 136 halves (272 B) -> conflict-free ldmatrix.
#define PAD 136
#define SM_AH 0
#define SM_AL (SM_AH + 64 * PAD * 2)            // 17408
#define SM_BH (SM_AL + 64 * PAD * 2)            // 34816
#define SM_BL (SM_BH + 128 * PAD * 2)           // 69632
#define SM_TOT (SM_BL + 128 * PAD * 2)          // 104448

__global__ __launch_bounds__(256, 2)
void gemm_mma(const float* __restrict__ feat,
              const float* __restrict__ bias,
              float* __restrict__ out, int N) {
    extern __shared__ char smem[];
    const uint32_t sb = smem_u32(smem);
    const int t = threadIdx.x;
    const int w = t >> 5, l = t & 31;
    const int row0 = blockIdx.x * 64;
    const int half = blockIdx.y;

    // ---- A tile: 64x128 f32 -> bf16 hi/lo in smem --------------------------
#pragma unroll
    for (int i = 0; i < 8; i++) {
        int idx = t + (i << 8);            // 0..2047 float4s
        int row = idx >> 5, kq = idx & 31; // k = kq*4
        int grow = row0 + row;
        float4 v = make_float4(0.f, 0.f, 0.f, 0.f);
        if (grow < N) v = ((const float4*)feat)[(size_t)grow * 32 + kq];

        __nv_bfloat16 hx = __float2bfloat16(v.x), hy = __float2bfloat16(v.y);
        __nv_bfloat16 hz = __float2bfloat16(v.z), hw = __float2bfloat16(v.w);
        __nv_bfloat162 h01 = __halves2bfloat162(hx, hy);
        __nv_bfloat162 h23 = __halves2bfloat162(hz, hw);
        __nv_bfloat162 l01 = __halves2bfloat162(
            __float2bfloat16(v.x - __bfloat162float(hx)),
            __float2bfloat16(v.y - __bfloat162float(hy)));
        __nv_bfloat162 l23 = __halves2bfloat162(
            __float2bfloat16(v.z - __bfloat162float(hz)),
            __float2bfloat16(v.w - __bfloat162float(hw)));

        int off = row * (PAD * 2) + kq * 8;   // bytes
        *(__nv_bfloat162*)(smem + SM_AH + off)     = h01;
        *(__nv_bfloat162*)(smem + SM_AH + off + 4) = h23;
        *(__nv_bfloat162*)(smem + SM_AL + off)     = l01;
        *(__nv_bfloat162*)(smem + SM_AL + off + 4) = l23;
    }

    // ---- B tiles: pre-split bf16 [n][k] -> padded smem ---------------------
    {
        const uint4* srcH = (const uint4*)(half ? g_BhL : g_BhW);
        const uint4* srcL = (const uint4*)(half ? g_BlL : g_BlW);
#pragma unroll
        for (int i = 0; i < 8; i++) {
            int idx = t + (i << 8);            // 0..2047 uint4s
            int n = idx >> 4, kq = idx & 15;   // 8 halves per uint4
            int off = n * (PAD * 2) + kq * 16;
            *(uint4*)(smem + SM_BH + off) = srcH[idx];
            *(uint4*)(smem + SM_BL + off) = srcL[idx];
        }
    }
    __syncthreads();

    // ---- mainloop ----------------------------------------------------------
    const int mbase = (w >> 2) * 32;       // 0 or 32
    const int nbase = (w & 3) * 32;        // 0,32,64,96

    // lane-dependent ldmatrix address components (bytes)
    const uint32_t aRow = (uint32_t)(mbase + (l & 15)) * (PAD * 2) + (l >> 4) * 16;
    const uint32_t bRow = (uint32_t)(nbase + ((l >> 4) << 3) + (l & 7)) * (PAD * 2)
                        + (((l >> 3) & 1) << 4);

    float acc[2][4][4];
#pragma unroll
    for (int mt = 0; mt < 2; mt++)
#pragma unroll
        for (int nt = 0; nt < 4; nt++)
#pragma unroll
            for (int q = 0; q < 4; q++) acc[mt][nt][q] = 0.f;

#pragma unroll
    for (int ks = 0; ks < 8; ks++) {
        const uint32_t kOff = (uint32_t)ks * 32;   // 16 halves = 32 B
        uint32_t ah[2][4], al[2][4], bh[2][4], bl[2][4];
#pragma unroll
        for (int mt = 0; mt < 2; mt++) {
            uint32_t a0 = sb + aRow + (uint32_t)mt * 16 * (PAD * 2) + kOff;
            LDSM_X4(ah[mt][0], ah[mt][1], ah[mt][2], ah[mt][3], a0 + SM_AH);
            LDSM_X4(al[mt][0], al[mt][1], al[mt][2], al[mt][3], a0 + SM_AL);
        }
#pragma unroll
        for (int np = 0; np < 2; np++) {
            uint32_t b0 = sb + bRow + (uint32_t)np * 16 * (PAD * 2) + kOff;
            LDSM_X4(bh[np][0], bh[np][1], bh[np][2], bh[np][3], b0 + SM_BH);
            LDSM_X4(bl[np][0], bl[np][1], bl[np][2], bl[np][3], b0 + SM_BL);
        }
#pragma unroll
        for (int mt = 0; mt < 2; mt++)
#pragma unroll
            for (int np = 0; np < 2; np++)
#pragma unroll
                for (int s = 0; s < 2; s++) {
                    int nt = np * 2 + s;
                    MMA16816(acc[mt][nt], ah[mt], bh[np][2 * s], bh[np][2 * s + 1]);
                    MMA16816(acc[mt][nt], al[mt], bh[np][2 * s], bh[np][2 * s + 1]);
                    MMA16816(acc[mt][nt], ah[mt], bl[np][2 * s], bl[np][2 * s + 1]);
                }
    }

    // ---- epilogue ----------------------------------------------------------
    // d frag: {d0,d1} -> (row l/4,   col (l&3)*2), {d2,d3} -> (row l/4 + 8, col)
    float* dst = half ? out : g_transformed;
#pragma unroll
    for (int mt = 0; mt < 2; mt++) {
        int r0 = row0 + mbase + mt * 16 + (l >> 2);
#pragma unroll
        for (int nt = 0; nt < 4; nt++) {
            int col = nbase + nt * 8 + (l & 3) * 2;
            float bx = 0.f, by = 0.f;
            if (half) { bx = bias[col]; by = bias[col + 1]; }
            if (r0 < N)
                *(float2*)&dst[(size_t)r0 * D + col] =
                    make_float2(acc[mt][nt][0] + bx, acc[mt][nt][1] + by);
            if (r0 + 8 < N)
                *(float2*)&dst[(size_t)(r0 + 8) * D + col] =
                    make_float2(acc[mt][nt][2] + bx, acc[mt][nt][3] + by);
        }
    }
}

// ---------------- edge scatter (unchanged: LTS-bound) -----------------------
__global__ void scatter_edges(const int* __restrict__ src,
                              const int* __restrict__ dst,
                              float* __restrict__ out, int E) {
    const int EPW = 4;
    const int gw = (int)((blockIdx.x * blockDim.x + threadIdx.x) >> 5);
    const int lane = threadIdx.x & 31;
    const int e0 = gw * EPW;
    if (e0 >= E) return;
    const int cnt = (E - e0 < EPW) ? (E - e0) : EPW;

    float4 v[EPW];
    float* p[EPW];
#pragma unroll
    for (int i = 0; i < EPW; i++) {
        if (i < cnt) {
            int s = __ldg(src + e0 + i);
            int d = __ldg(dst + e0 + i);
            v[i] = *reinterpret_cast<const float4*>(
                g_transformed + (size_t)s * D + lane * 4);
            p[i] = out + (size_t)d * D + lane * 4;
        }
    }
#pragma unroll
    for (int i = 0; i < EPW; i++) {
        if (i < cnt) {
            asm volatile("red.global.add.v4.f32 [%0], {%1, %2, %3, %4};"
                         :: "l"(p[i]), "f"(v[i].x), "f"(v[i].y), "f"(v[i].z),
                            "f"(v[i].w) : "memory");
        }
    }
}

extern "C" void kernel_launch(void* const* d_in, const int* in_sizes, int n_in,
                              void* d_out, int out_size) {
    const float* feat = (const float*)d_in[0];   // [N, 128]
    const float* W    = (const float*)d_in[1];   // [128, 128]
    const float* bias = (const float*)d_in[2];   // [128]
    const float* LW   = (const float*)d_in[3];   // [128, 128]
    const int*   src  = (const int*)d_in[4];     // [E]
    const int*   dst  = (const int*)d_in[5];     // [E]
    float* out = (float*)d_out;                  // [N, 128]

    const int N = in_sizes[0] / D;
    const int E = in_sizes[4];

    cudaFuncSetAttribute(gemm_mma, cudaFuncAttributeMaxDynamicSharedMemorySize,
                         SM_TOT);

    // 0) split + transpose weights to bf16 hi/lo
    prep_B<<<128, 256>>>(W, LW);

    // 1) T = feat@W ; out = feat@LW + bias  (HMMA, bf16 hi/lo 3-term)
    dim3 grid((N + 63) / 64, 2);
    gemm_mma<<<grid, 256, SM_TOT>>>(feat, bias, out, N);

    // 2) out[dst] += T[src]
    const int warps = (E + 3) / 4;
    const int blocks = (warps * 32 + 255) / 256;
    scatter_edges<<<blocks, 256>>>(src, dst, out, E);
}

// round 11
// speedup vs baseline: 2.3974x; 1.0435x over previous
#include <cuda_runtime.h>
#include <cuda_bf16.h>
#include <cuda_fp16.h>
#include <cstdint>

#define NODES_MAX 50000
#define D 128

typedef unsigned long long ull;

// ---------------- scratch (__device__ globals: allocation-free rule) --------
// T = feat @ W, stored fp16 (halves scatter read traffic; atomics stay fp32)
__device__ __half g_transformed[(size_t)NODES_MAX * D];   // 12.8 MB
// Pre-split weights, transposed to [n][k] (B^T layout), bf16 hi/lo
__device__ __nv_bfloat16 g_BhW[128 * 128];
__device__ __nv_bfloat16 g_BlW[128 * 128];
__device__ __nv_bfloat16 g_BhL[128 * 128];
__device__ __nv_bfloat16 g_BlL[128 * 128];

// ---------------- prep: [W|LW]^T -> bf16 hi/lo (coalesced reads) ------------
__global__ void prep_B(const float* __restrict__ W, const float* __restrict__ LW) {
    int i = blockIdx.x * blockDim.x + threadIdx.x;
    if (i >= 32768) return;
    const float* M = (i < 16384) ? W : LW;
    __nv_bfloat16* Bh = (i < 16384) ? g_BhW : g_BhL;
    __nv_bfloat16* Bl = (i < 16384) ? g_BlW : g_BlL;
    int j = i & 16383;
    int k = j >> 7, n = j & 127;
    float w = M[j];                           // coalesced read of M[k][n]
    __nv_bfloat16 hi = __float2bfloat16(w);
    __nv_bfloat16 lo = __float2bfloat16(w - __bfloat162float(hi));
    Bh[n * 128 + k] = hi;                     // scattered 2B writes (latency-hidden)
    Bl[n * 128 + k] = lo;
}

// ---------------- helpers ---------------------------------------------------
__device__ __forceinline__ uint32_t smem_u32(const void* p) {
    uint32_t a;
    asm("{ .reg .u64 t; cvta.to.shared.u64 t, %1; cvt.u32.u64 %0, t; }"
        : "=r"(a) : "l"(p));
    return a;
}

#define LDSM_X4(r0, r1, r2, r3, a) \
    asm volatile("ldmatrix.sync.aligned.m8n8.x4.shared.b16 {%0,%1,%2,%3}, [%4];" \
        : "=r"(r0), "=r"(r1), "=r"(r2), "=r"(r3) : "r"(a))

#define MMA16816(d, a, b0, b1) \
    asm volatile("mma.sync.aligned.m16n8k16.row.col.f32.bf16.bf16.f32 " \
        "{%0,%1,%2,%3}, {%4,%5,%6,%7}, {%8,%9}, {%0,%1,%2,%3};" \
        : "+f"((d)[0]), "+f"((d)[1]), "+f"((d)[2]), "+f"((d)[3]) \
        : "r"((a)[0]), "r"((a)[1]), "r"((a)[2]), "r"((a)[3]), \
          "r"(b0), "r"(b1))

// ---------------- tensor-core (mma.sync) fused GEMM -------------------------
// Grid (782, 2). blockIdx.y = 0: cols = W  -> g_transformed (fp16)
//                blockIdx.y = 1: cols = LW -> out (+bias, fp32)
// CTA: 256 threads, 64 rows x 128 cols. Warp (w = wm*4 + wn): 32x32 tile.
// Precision: A,B split to bf16 hi/lo; D = AhBh + AlBh + AhBl, fp32 accum.
// SMEM rows padded to 136 halves (272 B) -> conflict-free ldmatrix.
#define PAD 136
#define SM_AH 0
#define SM_AL (SM_AH + 64 * PAD * 2)            // 17408
#define SM_BH (SM_AL + 64 * PAD * 2)            // 34816
#define SM_BL (SM_BH + 128 * PAD * 2)           // 69632
#define SM_TOT (SM_BL + 128 * PAD * 2)          // 104448

__global__ __launch_bounds__(256, 2)
void gemm_mma(const float* __restrict__ feat,
              const float* __restrict__ bias,
              float* __restrict__ out, int N) {
    extern __shared__ char smem[];
    const uint32_t sb = smem_u32(smem);
    const int t = threadIdx.x;
    const int w = t >> 5, l = t & 31;
    const int row0 = blockIdx.x * 64;
    const int half = blockIdx.y;

    // ---- A tile: 64x128 f32 -> bf16 hi/lo in smem --------------------------
#pragma unroll
    for (int i = 0; i < 8; i++) {
        int idx = t + (i << 8);            // 0..2047 float4s
        int row = idx >> 5, kq = idx & 31; // k = kq*4
        int grow = row0 + row;
        float4 v = make_float4(0.f, 0.f, 0.f, 0.f);
        if (grow < N) v = ((const float4*)feat)[(size_t)grow * 32 + kq];

        __nv_bfloat16 hx = __float2bfloat16(v.x), hy = __float2bfloat16(v.y);
        __nv_bfloat16 hz = __float2bfloat16(v.z), hw = __float2bfloat16(v.w);
        __nv_bfloat162 h01 = __halves2bfloat162(hx, hy);
        __nv_bfloat162 h23 = __halves2bfloat162(hz, hw);
        __nv_bfloat162 l01 = __halves2bfloat162(
            __float2bfloat16(v.x - __bfloat162float(hx)),
            __float2bfloat16(v.y - __bfloat162float(hy)));
        __nv_bfloat162 l23 = __halves2bfloat162(
            __float2bfloat16(v.z - __bfloat162float(hz)),
            __float2bfloat16(v.w - __bfloat162float(hw)));

        int off = row * (PAD * 2) + kq * 8;   // bytes
        *(__nv_bfloat162*)(smem + SM_AH + off)     = h01;
        *(__nv_bfloat162*)(smem + SM_AH + off + 4) = h23;
        *(__nv_bfloat162*)(smem + SM_AL + off)     = l01;
        *(__nv_bfloat162*)(smem + SM_AL + off + 4) = l23;
    }

    // ---- B tiles: pre-split bf16 [n][k] -> padded smem ---------------------
    {
        const uint4* srcH = (const uint4*)(half ? g_BhL : g_BhW);
        const uint4* srcL = (const uint4*)(half ? g_BlL : g_BlW);
#pragma unroll
        for (int i = 0; i < 8; i++) {
            int idx = t + (i << 8);            // 0..2047 uint4s
            int n = idx >> 4, kq = idx & 15;   // 8 halves per uint4
            int off = n * (PAD * 2) + kq * 16;
            *(uint4*)(smem + SM_BH + off) = srcH[idx];
            *(uint4*)(smem + SM_BL + off) = srcL[idx];
        }
    }
    __syncthreads();

    // ---- mainloop ----------------------------------------------------------
    const int mbase = (w >> 2) * 32;       // 0 or 32
    const int nbase = (w & 3) * 32;        // 0,32,64,96

    const uint32_t aRow = (uint32_t)(mbase + (l & 15)) * (PAD * 2) + (l >> 4) * 16;
    const uint32_t bRow = (uint32_t)(nbase + ((l >> 4) << 3) + (l & 7)) * (PAD * 2)
                        + (((l >> 3) & 1) << 4);

    float acc[2][4][4];
#pragma unroll
    for (int mt = 0; mt < 2; mt++)
#pragma unroll
        for (int nt = 0; nt < 4; nt++)
#pragma unroll
            for (int q = 0; q < 4; q++) acc[mt][nt][q] = 0.f;

#pragma unroll
    for (int ks = 0; ks < 8; ks++) {
        const uint32_t kOff = (uint32_t)ks * 32;   // 16 halves = 32 B
        uint32_t ah[2][4], al[2][4], bh[2][4], bl[2][4];
#pragma unroll
        for (int mt = 0; mt < 2; mt++) {
            uint32_t a0 = sb + aRow + (uint32_t)mt * 16 * (PAD * 2) + kOff;
            LDSM_X4(ah[mt][0], ah[mt][1], ah[mt][2], ah[mt][3], a0 + SM_AH);
            LDSM_X4(al[mt][0], al[mt][1], al[mt][2], al[mt][3], a0 + SM_AL);
        }
#pragma unroll
        for (int np = 0; np < 2; np++) {
            uint32_t b0 = sb + bRow + (uint32_t)np * 16 * (PAD * 2) + kOff;
            LDSM_X4(bh[np][0], bh[np][1], bh[np][2], bh[np][3], b0 + SM_BH);
            LDSM_X4(bl[np][0], bl[np][1], bl[np][2], bl[np][3], b0 + SM_BL);
        }
#pragma unroll
        for (int mt = 0; mt < 2; mt++)
#pragma unroll
            for (int np = 0; np < 2; np++)
#pragma unroll
                for (int s = 0; s < 2; s++) {
                    int nt = np * 2 + s;
                    MMA16816(acc[mt][nt], ah[mt], bh[np][2 * s], bh[np][2 * s + 1]);
                    MMA16816(acc[mt][nt], al[mt], bh[np][2 * s], bh[np][2 * s + 1]);
                    MMA16816(acc[mt][nt], ah[mt], bl[np][2 * s], bl[np][2 * s + 1]);
                }
    }

    // ---- epilogue ----------------------------------------------------------
    // d frag: {d0,d1} -> (row l/4, col (l&3)*2), {d2,d3} -> (row l/4 + 8, col)
#pragma unroll
    for (int mt = 0; mt < 2; mt++) {
        int r0 = row0 + mbase + mt * 16 + (l >> 2);
#pragma unroll
        for (int nt = 0; nt < 4; nt++) {
            int col = nbase + nt * 8 + (l & 3) * 2;
            if (half) {
                float bx = bias[col], by = bias[col + 1];
                if (r0 < N)
                    *(float2*)&out[(size_t)r0 * D + col] =
                        make_float2(acc[mt][nt][0] + bx, acc[mt][nt][1] + by);
                if (r0 + 8 < N)
                    *(float2*)&out[(size_t)(r0 + 8) * D + col] =
                        make_float2(acc[mt][nt][2] + bx, acc[mt][nt][3] + by);
            } else {
                if (r0 < N)
                    *(__half2*)&g_transformed[(size_t)r0 * D + col] =
                        __floats2half2_rn(acc[mt][nt][0], acc[mt][nt][1]);
                if (r0 + 8 < N)
                    *(__half2*)&g_transformed[(size_t)(r0 + 8) * D + col] =
                        __floats2half2_rn(acc[mt][nt][2], acc[mt][nt][3]);
            }
        }
    }
}

// ---------------- edge scatter (fp16 reads, fp32 atomics) -------------------
// One warp per edge-quad. Lane owns 4 columns: 8B fp16 read, one
// red.global.add.v4.f32 (16B) per edge. Read traffic halved vs fp32 T.
__global__ void scatter_edges(const int* __restrict__ src,
                              const int* __restrict__ dst,
                              float* __restrict__ out, int E) {
    const int EPW = 4;
    const int gw = (int)((blockIdx.x * blockDim.x + threadIdx.x) >> 5);
    const int lane = threadIdx.x & 31;
    const int e0 = gw * EPW;
    if (e0 >= E) return;
    const int cnt = (E - e0 < EPW) ? (E - e0) : EPW;

    uint2 raw[EPW];
    float* p[EPW];
#pragma unroll
    for (int i = 0; i < EPW; i++) {
        if (i < cnt) {
            int s = __ldg(src + e0 + i);
            int d = __ldg(dst + e0 + i);
            raw[i] = *reinterpret_cast<const uint2*>(
                g_transformed + (size_t)s * D + lane * 4);
            p[i] = out + (size_t)d * D + lane * 4;
        }
    }
#pragma unroll
    for (int i = 0; i < EPW; i++) {
        if (i < cnt) {
            float2 f0 = __half22float2(*reinterpret_cast<__half2*>(&raw[i].x));
            float2 f1 = __half22float2(*reinterpret_cast<__half2*>(&raw[i].y));
            asm volatile("red.global.add.v4.f32 [%0], {%1, %2, %3, %4};"
                         :: "l"(p[i]), "f"(f0.x), "f"(f0.y), "f"(f1.x),
                            "f"(f1.y) : "memory");
        }
    }
}

extern "C" void kernel_launch(void* const* d_in, const int* in_sizes, int n_in,
                              void* d_out, int out_size) {
    const float* feat = (const float*)d_in[0];   // [N, 128]
    const float* W    = (const float*)d_in[1];   // [128, 128]
    const float* bias = (const float*)d_in[2];   // [128]
    const float* LW   = (const float*)d_in[3];   // [128, 128]
    const int*   src  = (const int*)d_in[4];     // [E]
    const int*   dst  = (const int*)d_in[5];     // [E]
    float* out = (float*)d_out;                  // [N, 128]

    const int N = in_sizes[0] / D;
    const int E = in_sizes[4];

    cudaFuncSetAttribute(gemm_mma, cudaFuncAttributeMaxDynamicSharedMemorySize,
                         SM_TOT);

    // 0) split + transpose weights to bf16 hi/lo
    prep_B<<<128, 256>>>(W, LW);

    // 1) T = feat@W (fp16) ; out = feat@LW + bias  (HMMA, bf16 hi/lo 3-term)
    dim3 grid((N + 63) / 64, 2);
    gemm_mma<<<grid, 256, SM_TOT>>>(feat, bias, out, N);

    // 2) out[dst] += T[src]
    const int warps = (E + 3) / 4;
    const int blocks = (warps * 32 + 255) / 256;
    scatter_edges<<<blocks, 256>>>(src, dst, out, E);
}